// round 12
// baseline (speedup 1.0000x reference)
#include <cuda_runtime.h>
#include <cuda_bf16.h>
#include <math.h>
#include <stdint.h>

#define BB 32
#define TT 512
#define EE 256
#define UU 512
#define U3 1536
#define GRID 64          // recurrence blocks (each handles BOTH directions)
#define USTR 520         // U SMEM ushort stride (260 words, conflict-free)
#define ASTR 40          // xproj SMEM ushort stride

// ---------------- device scratch (static; no runtime allocation) ------------
__device__ float          g_xproj[2][BB][TT][U3];  // x@W + b_in per direction
__device__ unsigned short g_hh[2][2][BB][UU];      // h hi bf16, double-buffered
__device__ unsigned short g_hl[2][2][BB][UU];      // h lo bf16
__device__ unsigned       g_cnt[2][TT];            // barrier counters (memset 0)

// ---------------- bf16 split helpers ----------------------------------------
__device__ __forceinline__ unsigned short bf16_hi(float v) {
    return __bfloat16_as_ushort(__float2bfloat16_rn(v));
}
__device__ __forceinline__ void split2(float v, unsigned short& h, unsigned short& l) {
    h = bf16_hi(v);
    float fh = __uint_as_float((unsigned)h << 16);
    l = bf16_hi(v - fh);
}
__device__ __forceinline__ float joinhl(unsigned short h, unsigned short l) {
    return __uint_as_float((unsigned)h << 16) + __uint_as_float((unsigned)l << 16);
}

// ---------------- bf16 mma helper (m16n8k16) ---------------------------------
__device__ __forceinline__ void mma_bf16(float* D,
                                         unsigned a0, unsigned a1, unsigned a2, unsigned a3,
                                         unsigned b0, unsigned b1) {
    asm volatile(
        "mma.sync.aligned.m16n8k16.row.col.f32.bf16.bf16.f32 "
        "{%0,%1,%2,%3}, {%4,%5,%6,%7}, {%8,%9}, {%0,%1,%2,%3};"
        : "+f"(D[0]), "+f"(D[1]), "+f"(D[2]), "+f"(D[3])
        : "r"(a0), "r"(a1), "r"(a2), "r"(a3), "r"(b0), "r"(b1));
}

// ---------------- Kernel A: x_proj = emb[tokens] @ W + b_in (bf16x3 MMA) ----
__global__ void __launch_bounds__(256) xproj_kernel(
    const int* __restrict__ tokens,
    const float* __restrict__ emb,
    const float* __restrict__ W_fw, const float* __restrict__ b_in_fw,
    const float* __restrict__ W_bw, const float* __restrict__ b_in_bw)
{
    __shared__ __align__(16) unsigned short SAh[128 * ASTR];
    __shared__ __align__(16) unsigned short SAl[128 * ASTR];
    __shared__ __align__(16) unsigned short SBh[64 * ASTR];
    __shared__ __align__(16) unsigned short SBl[64 * ASTR];
    __shared__ int toks[128];

    const int d  = blockIdx.z;
    const float* __restrict__ Wp = d ? W_bw : W_fw;
    const float* __restrict__ bp = d ? b_in_bw : b_in_fw;
    const int n0 = blockIdx.x * 64;
    const int m0 = blockIdx.y * 128;
    const int tid = threadIdx.x;
    const int wid = tid >> 5;
    const int lane = tid & 31;
    const int gr = lane >> 2;
    const int gc = lane & 3;

    if (tid < 128) toks[tid] = tokens[m0 + tid];
    __syncthreads();

    const unsigned* SAhw = (const unsigned*)SAh;
    const unsigned* SAlw = (const unsigned*)SAl;
    const unsigned* SBhw = (const unsigned*)SBh;
    const unsigned* SBlw = (const unsigned*)SBl;

    float D[8][4];
#pragma unroll
    for (int j = 0; j < 8; j++)
#pragma unroll
        for (int q = 0; q < 4; q++) D[j][q] = 0.f;

    const int arow = tid >> 1;
    const int ak   = (tid & 1) * 16;
    const int bk   = tid >> 3;
    const int bn   = (tid & 7) * 8;

    const int baseA0 = (wid * 16 + gr) * (ASTR/2);
    const int baseA1 = baseA0 + 8 * (ASTR/2);

    for (int k0 = 0; k0 < EE; k0 += 32) {
        {
            const float* src = emb + (size_t)toks[arow] * EE + k0 + ak;
            float4 v0 = *(const float4*)(src);
            float4 v1 = *(const float4*)(src + 4);
            float4 v2 = *(const float4*)(src + 8);
            float4 v3 = *(const float4*)(src + 12);
            float vv[16] = {v0.x,v0.y,v0.z,v0.w, v1.x,v1.y,v1.z,v1.w,
                            v2.x,v2.y,v2.z,v2.w, v3.x,v3.y,v3.z,v3.w};
            unsigned short* ph = SAh + arow * ASTR + ak;
            unsigned short* pl = SAl + arow * ASTR + ak;
#pragma unroll
            for (int i = 0; i < 16; i++) {
                unsigned short h, l;
                split2(vv[i], h, l);
                ph[i] = h; pl[i] = l;
            }
        }
        {
            const float* src = Wp + (size_t)(k0 + bk) * U3 + n0 + bn;
            float4 v0 = *(const float4*)(src);
            float4 v1 = *(const float4*)(src + 4);
            float vv[8] = {v0.x,v0.y,v0.z,v0.w, v1.x,v1.y,v1.z,v1.w};
#pragma unroll
            for (int c = 0; c < 8; c++) {
                unsigned short h, l;
                split2(vv[c], h, l);
                SBh[(bn + c) * ASTR + bk] = h;
                SBl[(bn + c) * ASTR + bk] = l;
            }
        }
        __syncthreads();

#pragma unroll
        for (int kt = 0; kt < 2; kt++) {
            int kw = kt * 8;
            unsigned ah0 = SAhw[baseA0 + kw + gc];
            unsigned ah1 = SAhw[baseA1 + kw + gc];
            unsigned ah2 = SAhw[baseA0 + kw + gc + 4];
            unsigned ah3 = SAhw[baseA1 + kw + gc + 4];
            unsigned al0 = SAlw[baseA0 + kw + gc];
            unsigned al1 = SAlw[baseA1 + kw + gc];
            unsigned al2 = SAlw[baseA0 + kw + gc + 4];
            unsigned al3 = SAlw[baseA1 + kw + gc + 4];
#pragma unroll
            for (int j = 0; j < 8; j++) {
                int ub = (j * 8 + gr) * (ASTR/2) + kw + gc;
                unsigned bh0 = SBhw[ub], bh1 = SBhw[ub + 4];
                unsigned bl0 = SBlw[ub], bl1 = SBlw[ub + 4];
                mma_bf16(D[j], ah0, ah1, ah2, ah3, bh0, bh1);
                mma_bf16(D[j], ah0, ah1, ah2, ah3, bl0, bl1);
                mma_bf16(D[j], al0, al1, al2, al3, bh0, bh1);
            }
        }
        __syncthreads();
    }

    float* gx = &g_xproj[0][0][0][0];
    const size_t mbase = (size_t)d * (BB*TT) + m0 + wid * 16;
#pragma unroll
    for (int j = 0; j < 8; j++) {
        int cc = n0 + j * 8 + gc * 2;
        float2 bias = *(const float2*)(bp + cc);
        float2 vlo = { D[j][0] + bias.x, D[j][1] + bias.y };
        float2 vhi = { D[j][2] + bias.x, D[j][3] + bias.y };
        *(float2*)(gx + (mbase + gr)     * U3 + cc) = vlo;
        *(float2*)(gx + (mbase + gr + 8) * U3 + cc) = vhi;
    }
}

// ---------------- Kernel B: dual-direction persistent GRU recurrence --------
// 64 blocks, 256 threads = 8 warps (2 m x 4 ksplit). Each block owns units
// [bid*8, +8) of BOTH directions and pipelines fw/bw steps so each barrier
// wait is hidden under the other direction's compute.
// h staged swizzled (no pad); psum aliases the OTHER direction's h region.
#define SMEM_BYTES ((4*32*512 + 4*24*USTR) * 2)

__device__ __forceinline__ void barrier_arrive(int d, int ts, int tid) {
    __syncthreads();
    if (tid == 0) { __threadfence(); atomicAdd(&g_cnt[d][ts], 1u); }
}
__device__ __forceinline__ void barrier_wait(int d, int ts, int tid) {
    if (tid == 0) {
        volatile unsigned* c = &g_cnt[d][ts];
        while (*c < (unsigned)GRID) { }
        __threadfence();
    }
    __syncthreads();
}

__device__ __forceinline__ void gru_step_dir(
    const int d, const int t, const int buf,
    unsigned short* __restrict__ hsH, unsigned short* __restrict__ hsL,
    const unsigned short* __restrict__ UsH, const unsigned short* __restrict__ UsL,
    float* __restrict__ psum,
    const int* __restrict__ tokens, const float* __restrict__ gx,
    float* __restrict__ out,
    const float brz, const float brr, const float brh,
    const int u0, const int tid, const int lane,
    const int mi, const int kh, const int gr, const int gc,
    const int eb, const int eu)
{
    unsigned* hsHw = (unsigned*)hsH;
    unsigned* hsLw = (unsigned*)hsL;
    const unsigned* UsHw = (const unsigned*)UsH;
    const unsigned* UsLw = (const unsigned*)UsL;

    // ---- warp-local h staging (swizzled, stride 256 words) ----
    const int srow = mi * 16;
    const int skw  = kh * 64;        // word base of this warp's k range
    const int sk8  = kh * 16;        // uint4 base within 512-ushort row
#pragma unroll
    for (int i = 0; i < 8; i++) {
        int uid  = lane + 32 * i;            // 0..255
        int row  = srow + (uid >> 4);
        int slot = uid & 15;
        int wsw  = (skw + slot * 4) ^ ((row & 7) << 2);
        uint4 vH = __ldcg((const uint4*)&g_hh[d][buf][row][0] + sk8 + slot);
        uint4 vL = __ldcg((const uint4*)&g_hl[d][buf][row][0] + sk8 + slot);
        *(uint4*)(hsHw + row * 256 + wsw) = vH;
        *(uint4*)(hsLw + row * 256 + wsw) = vL;
    }
    // prefetch epilogue inputs
    size_t xb = ((size_t)d * (BB*TT) + (size_t)eb * TT + t) * U3;
    float xz = gx[xb + u0 + eu];
    float xr = gx[xb + 512 + u0 + eu];
    float xh = gx[xb + 1024 + u0 + eu];
    int   mt = (tokens[eb * TT + t] != 0);
    __syncwarp();

    // ---- bf16x3 dot: 8 k16-tiles, 3 n-tiles, 9 independent acc sets ----
    float Dhh[3][4], Dhl[3][4], Dlh[3][4];
#pragma unroll
    for (int j = 0; j < 3; j++)
#pragma unroll
        for (int q = 0; q < 4; q++) { Dhh[j][q] = 0.f; Dhl[j][q] = 0.f; Dlh[j][q] = 0.f; }

    const int xrA = gr << 2;
    const int rbase0 = (mi*16 + gr) * 256;
    const int rbase1 = rbase0 + 8 * 256;
    const int kwbase = kh * 64;
#pragma unroll 2
    for (int kt = 0; kt < 8; kt++) {
        int kw = kwbase + kt * 8;
        int c0 = (kw + gc) ^ xrA;
        int c1 = (kw + gc + 4) ^ xrA;
        unsigned ah0 = hsHw[rbase0 + c0];
        unsigned ah1 = hsHw[rbase1 + c0];
        unsigned ah2 = hsHw[rbase0 + c1];
        unsigned ah3 = hsHw[rbase1 + c1];
        unsigned al0 = hsLw[rbase0 + c0];
        unsigned al1 = hsLw[rbase1 + c0];
        unsigned al2 = hsLw[rbase0 + c1];
        unsigned al3 = hsLw[rbase1 + c1];
#pragma unroll
        for (int j = 0; j < 3; j++) {
            int ub = (j*8 + gr) * (USTR/2) + kw + gc;
            unsigned bh0 = UsHw[ub], bh1 = UsHw[ub + 4];
            unsigned bl0 = UsLw[ub], bl1 = UsLw[ub + 4];
            mma_bf16(Dhh[j], ah0, ah1, ah2, ah3, bh0, bh1);
            mma_bf16(Dhl[j], ah0, ah1, ah2, ah3, bl0, bl1);
            mma_bf16(Dlh[j], al0, al1, al2, al3, bh0, bh1);
        }
    }

    float D[3][4];
#pragma unroll
    for (int j = 0; j < 3; j++)
#pragma unroll
        for (int q = 0; q < 4; q++)
            D[j][q] = Dhh[j][q] + Dhl[j][q] + Dlh[j][q];

    // ---- two-phase k-split reduction (psum aliases other dir's hs) ----
    const int r0 = mi*16 + gr;
    const int r1 = r0 + 8;
    if (kh > 0) {
#pragma unroll
        for (int j = 0; j < 3; j++) {
            int cc = j*8 + gc*2;
            *(float2*)&psum[((kh-1)*32 + r0)*24 + cc] = make_float2(D[j][0], D[j][1]);
            *(float2*)&psum[((kh-1)*32 + r1)*24 + cc] = make_float2(D[j][2], D[j][3]);
        }
    }
    __syncthreads();
    if (kh == 0) {
#pragma unroll
        for (int s = 0; s < 3; s++)
#pragma unroll
            for (int j = 0; j < 3; j++) {
                int cc = j*8 + gc*2;
                float2 p0 = *(const float2*)&psum[(s*32 + r0)*24 + cc];
                float2 p1 = *(const float2*)&psum[(s*32 + r1)*24 + cc];
                D[j][0] += p0.x; D[j][1] += p0.y;
                D[j][2] += p1.x; D[j][3] += p1.y;
            }
#pragma unroll
        for (int j = 0; j < 3; j++) {
            int cc = j*8 + gc*2;
            *(float2*)&psum[r0*24 + cc] = make_float2(D[j][0], D[j][1]);
            *(float2*)&psum[r1*24 + cc] = make_float2(D[j][2], D[j][3]);
        }
    }
    __syncthreads();

    // ---- epilogue: all 256 threads, each = one (batch, unit) ----
    {
        float hz = psum[eb*24 + 0  + eu] + brz;
        float hr = psum[eb*24 + 8  + eu] + brr;
        float hh = psum[eb*24 + 16 + eu] + brh;

        float z    = __fdividef(1.f, 1.f + __expf(-(xz + hz)));
        float r    = __fdividef(1.f, 1.f + __expf(-(xr + hr)));
        float ta   = xh + r * hh;
        float cand = 1.f - __fdividef(2.f, __expf(2.f * ta) + 1.f);

        int wcol = (u0 + eu) >> 1;
        int wsw  = wcol ^ ((eb & 7) << 2);
        unsigned wH = hsHw[eb*256 + wsw];
        unsigned wL = hsLw[eb*256 + wsw];
        unsigned short hph = (eu & 1) ? (unsigned short)(wH >> 16) : (unsigned short)(wH & 0xFFFF);
        unsigned short hpl = (eu & 1) ? (unsigned short)(wL >> 16) : (unsigned short)(wL & 0xFFFF);
        float hp = joinhl(hph, hpl);

        float hn = z * hp + (1.f - z) * cand;
        if (!mt) hn = hp;

        unsigned short hnh, hnl;
        split2(hn, hnh, hnl);
        g_hh[d][buf ^ 1][eb][u0 + eu] = hnh;
        g_hl[d][buf ^ 1][eb][u0 + eu] = hnl;
        out[((size_t)eb * TT + t) * (2*UU) + (size_t)d * UU + u0 + eu] = hn;
    }
}

__global__ void __launch_bounds__(256, 1) gru_kernel(
    const int* __restrict__ tokens,
    const float* __restrict__ U_fw, const float* __restrict__ b_rec_fw,
    const float* __restrict__ U_bw, const float* __restrict__ b_rec_bw,
    float* __restrict__ out)
{
    extern __shared__ unsigned short smemus[];
    unsigned short* hsFH = smemus;               // [32][512] swizzled
    unsigned short* hsFL = hsFH + 32*512;
    unsigned short* hsBH = hsFL + 32*512;
    unsigned short* hsBL = hsBH + 32*512;
    unsigned short* UFH  = hsBL + 32*512;        // [24][520]
    unsigned short* UFL  = UFH + 24*USTR;
    unsigned short* UBH  = UFL + 24*USTR;
    unsigned short* UBL  = UBH + 24*USTR;
    float* psumF = (float*)hsBH;                 // alias: dead during fw phase
    float* psumB = (float*)hsFH;                 // alias: dead during bw phase

    const int bid = blockIdx.x;
    const int u0  = bid * 8;
    const int tid = threadIdx.x;
    const int wid = tid >> 5;
    const int lane = tid & 31;
    const int mi = wid & 1;
    const int kh = wid >> 1;
    const int gr = lane >> 2;
    const int gc = lane & 3;
    const int eb = tid >> 3, eu = tid & 7;

    // stage both U slices hi/lo once
    for (int idx = tid; idx < 24 * 512; idx += 256) {
        int c = idx >> 9;
        int k = idx & 511;
        int g = c >> 3;
        size_t off = (size_t)k * U3 + g * 512 + u0 + (c & 7);
        unsigned short h, l;
        split2(U_fw[off], h, l);
        UFH[c * USTR + k] = h; UFL[c * USTR + k] = l;
        split2(U_bw[off], h, l);
        UBH[c * USTR + k] = h; UBL[c * USTR + k] = l;
    }

    const float brzF = b_rec_fw[0*512 + u0 + eu];
    const float brrF = b_rec_fw[1*512 + u0 + eu];
    const float brhF = b_rec_fw[2*512 + u0 + eu];
    const float brzB = b_rec_bw[0*512 + u0 + eu];
    const float brrB = b_rec_bw[1*512 + u0 + eu];
    const float brhB = b_rec_bw[2*512 + u0 + eu];

    const float* gx = &g_xproj[0][0][0][0];

    __syncthreads();

    for (int ts = 0; ts < TT; ts++) {
        const int buf = ts & 1;

        // ---- forward direction step ----
        if (ts) barrier_wait(0, ts - 1, tid);
        gru_step_dir(0, ts, buf, hsFH, hsFL, UFH, UFL, psumF,
                     tokens, gx, out, brzF, brrF, brhF,
                     u0, tid, lane, mi, kh, gr, gc, eb, eu);
        barrier_arrive(0, ts, tid);

        // ---- backward direction step (its wait hides under fw compute) ----
        if (ts) barrier_wait(1, ts - 1, tid);
        gru_step_dir(1, TT - 1 - ts, buf, hsBH, hsBL, UBH, UBL, psumB,
                     tokens, gx, out, brzB, brrB, brhB,
                     u0, tid, lane, mi, kh, gr, gc, eb, eu);
        barrier_arrive(1, ts, tid);
    }
}

// ---------------- launch ----------------------------------------------------
extern "C" void kernel_launch(void* const* d_in, const int* in_sizes, int n_in,
                              void* d_out, int out_size)
{
    const int*   tokens   = (const int*)  d_in[0];
    const float* emb      = (const float*)d_in[1];
    const float* W_fw     = (const float*)d_in[2];
    const float* U_fw     = (const float*)d_in[3];
    const float* b_in_fw  = (const float*)d_in[4];
    const float* b_rec_fw = (const float*)d_in[5];
    const float* W_bw     = (const float*)d_in[6];
    const float* U_bw     = (const float*)d_in[7];
    const float* b_in_bw  = (const float*)d_in[8];
    const float* b_rec_bw = (const float*)d_in[9];
    float* out = (float*)d_out;

    void* p;
    cudaGetSymbolAddress(&p, g_hh);
    cudaMemsetAsync(p, 0, sizeof(g_hh));
    cudaGetSymbolAddress(&p, g_hl);
    cudaMemsetAsync(p, 0, sizeof(g_hl));
    cudaGetSymbolAddress(&p, g_cnt);
    cudaMemsetAsync(p, 0, sizeof(g_cnt));

    dim3 gA(U3 / 64, (BB * TT) / 128, 2);
    xproj_kernel<<<gA, 256>>>(tokens, emb, W_fw, b_in_fw, W_bw, b_in_bw);

    cudaFuncSetAttribute(gru_kernel,
                         cudaFuncAttributeMaxDynamicSharedMemorySize, SMEM_BYTES);
    gru_kernel<<<GRID, 256, SMEM_BYTES>>>(tokens, U_fw, b_rec_fw,
                                          U_bw, b_rec_bw, out);
}

// round 13
// speedup vs baseline: 1.8558x; 1.8558x over previous
#include <cuda_runtime.h>
#include <cuda_bf16.h>
#include <math.h>
#include <stdint.h>

#define BB 32
#define TT 512
#define EE 256
#define UU 512
#define U3 1536
#define NBLK 64          // blocks per direction in recurrence
#define RGRID (2*NBLK)   // total recurrence blocks
#define HSTR 520         // h SMEM ushort stride (260 words, mod32=4 conflict-free)
#define XSTR 264         // x SMEM ushort stride (132 words, mod32=4)
#define BSTR 776         // B=[W;U] SMEM ushort stride (388 words, mod32=4)

// ---------------- device scratch (static; no runtime allocation) ------------
__device__ unsigned short g_embh[(size_t)32000 * EE];  // emb hi bf16
__device__ unsigned short g_embl[(size_t)32000 * EE];  // emb lo bf16
__device__ int            g_tokT[TT * BB];             // tokens transposed [t][b]
__device__ unsigned short g_hh[2][2][BB][UU];          // h hi bf16, double-buffered
__device__ unsigned short g_hl[2][2][BB][UU];          // h lo bf16
__device__ unsigned       g_cnt[2][TT];                // barrier counters (memset 0)

// ---------------- bf16 split helpers ----------------------------------------
__device__ __forceinline__ unsigned short bf16_hi(float v) {
    return __bfloat16_as_ushort(__float2bfloat16_rn(v));
}
__device__ __forceinline__ void split2(float v, unsigned short& h, unsigned short& l) {
    h = bf16_hi(v);
    float fh = __uint_as_float((unsigned)h << 16);
    l = bf16_hi(v - fh);
}
__device__ __forceinline__ float joinhl(unsigned short h, unsigned short l) {
    return __uint_as_float((unsigned)h << 16) + __uint_as_float((unsigned)l << 16);
}

// ---------------- bf16 mma helper (m16n8k16) ---------------------------------
__device__ __forceinline__ void mma_bf16(float* D,
                                         unsigned a0, unsigned a1, unsigned a2, unsigned a3,
                                         unsigned b0, unsigned b1) {
    asm volatile(
        "mma.sync.aligned.m16n8k16.row.col.f32.bf16.bf16.f32 "
        "{%0,%1,%2,%3}, {%4,%5,%6,%7}, {%8,%9}, {%0,%1,%2,%3};"
        : "+f"(D[0]), "+f"(D[1]), "+f"(D[2]), "+f"(D[3])
        : "r"(a0), "r"(a1), "r"(a2), "r"(a3), "r"(b0), "r"(b1));
}

// ---------------- prep: split emb to bf16 hi/lo + transpose tokens ----------
__global__ void __launch_bounds__(256) prep_kernel(
    const int* __restrict__ tokens, const float* __restrict__ emb)
{
    int gid = blockIdx.x * 256 + threadIdx.x;
    size_t base = (size_t)gid * 4;
    float4 v = *(const float4*)(emb + base);
    unsigned short h, l;
    split2(v.x, h, l); g_embh[base+0] = h; g_embl[base+0] = l;
    split2(v.y, h, l); g_embh[base+1] = h; g_embl[base+1] = l;
    split2(v.z, h, l); g_embh[base+2] = h; g_embl[base+2] = l;
    split2(v.w, h, l); g_embh[base+3] = h; g_embl[base+3] = l;
    if (gid < BB * TT) {
        int b = gid >> 9, t = gid & 511;
        g_tokT[t * 32 + b] = tokens[gid];
    }
}

// ---------------- Kernel B: fused persistent GRU (x.W + h.U in one GEMM) ----
// 128 blocks (64/dir), 256 threads = 8 warps (2 m-tiles x 4 k-splits).
// Per step: P[32x24] = [x(t) || h(t-1)](32x768) * B(768x24), bf16x3 m16n8k16.
// x-slab staged per warp from pre-split emb BEFORE the barrier wait (hidden).
// Two-phase psum + single-counter barrier (R11-verified).
#define SMEM_BYTES ((32*HSTR + 32*XSTR + 24*BSTR) * 2 * 2 + 3*32*24*4)

__global__ void __launch_bounds__(256, 1) gru_kernel(
    const float* __restrict__ W_fw, const float* __restrict__ b_in_fw,
    const float* __restrict__ b_rec_fw,
    const float* __restrict__ W_bw, const float* __restrict__ b_in_bw,
    const float* __restrict__ b_rec_bw,
    const float* __restrict__ U_fw, const float* __restrict__ U_bw,
    float* __restrict__ out)
{
    extern __shared__ unsigned short smemus[];
    unsigned short* hsH = smemus;               // [32][520]
    unsigned short* hsL = hsH + 32*HSTR;
    unsigned short* xAH = hsL + 32*HSTR;        // [32][264]
    unsigned short* xAL = xAH + 32*XSTR;
    unsigned short* BH  = xAL + 32*XSTR;        // [24][776]  rows: k<256 = W, else U
    unsigned short* BL  = BH + 24*BSTR;
    float* psum = (float*)(BL + 24*BSTR);       // [3][32][24]

    unsigned* hsHw = (unsigned*)hsH;
    unsigned* hsLw = (unsigned*)hsL;
    unsigned* xAHw = (unsigned*)xAH;
    unsigned* xALw = (unsigned*)xAL;
    const unsigned* BHw = (const unsigned*)BH;
    const unsigned* BLw = (const unsigned*)BL;

    const int bid = blockIdx.x;
    const int d   = bid >> 6;
    const int jb  = bid & (NBLK - 1);
    const int u0  = jb * 8;
    const int tid = threadIdx.x;
    const int lane = tid & 31;
    const int wid = tid >> 5;
    const int mi = wid & 1;          // m-tile (rows mi*16 .. +15)
    const int kh = wid >> 1;         // k-split 0..3
    const int gr = lane >> 2;
    const int gc = lane & 3;

    const float* __restrict__ Wp = d ? W_bw : W_fw;
    const float* __restrict__ Uw = d ? U_bw : U_fw;
    const float* __restrict__ bi = d ? b_in_bw : b_in_fw;
    const float* __restrict__ br = d ? b_rec_bw : b_rec_fw;

    // stage B = [W(256) ; U(512)] hi/lo once (24 cols)
    for (int c = 0; c < 24; c++) {
        int g = c >> 3;
        int col = g * 512 + u0 + (c & 7);
        for (int k = tid; k < 768; k += 256) {
            float v = (k < 256) ? Wp[(size_t)k * U3 + col]
                                : Uw[(size_t)(k - 256) * U3 + col];
            unsigned short h, l;
            split2(v, h, l);
            BH[c * BSTR + k] = h;
            BL[c * BSTR + k] = l;
        }
    }

    // epilogue mapping (all 256 threads): batch eb, unit eu; fold b_in + b_rec
    const int eb = tid >> 3, eu = tid & 7;
    const float brz = bi[0*512 + u0 + eu] + br[0*512 + u0 + eu];
    const float brr = bi[1*512 + u0 + eu] + br[1*512 + u0 + eu];
    // candidate gate: x-part bias b_in adds outside, recurrent bias b_rec is
    // INSIDE r*(...): keep separate
    const float bih = bi[2*512 + u0 + eu];
    const float brh = br[2*512 + u0 + eu];

    const int base0 = (mi*16 + gr) * (HSTR/2);   // h word base rows gr/gr+8
    const int base1 = base0 + 8 * (HSTR/2);
    const int xb0   = (mi*16 + gr) * (XSTR/2);
    const int xb1   = xb0 + 8 * (XSTR/2);
    const int r0  = mi*16 + gr;
    const int r1  = r0 + 8;
    const int kwbase = kh * 64;                  // h k-range word base
    const int xkwbase = kh * 32;                 // x k-range word base
    const int srow = mi * 16;
    const int sk8  = kh * 16;                    // h staging uint4 base

    __syncthreads();

    for (int ts = 0; ts < TT; ts++) {
        const int t   = d ? (TT - 1 - ts) : ts;
        const int buf = ts & 1;

        // ---- stage x(t) slab (barrier-independent; fills the wait window) --
#pragma unroll
        for (int i = 0; i < 4; i++) {
            int uid  = lane + 32 * i;            // 0..127
            int row  = srow + (uid >> 3);        // 16 rows
            int slot = uid & 7;                  // uint4 slot in 64-ushort chunk
            int tok  = g_tokT[t * 32 + row];
            const uint4* sh = (const uint4*)(g_embh + (size_t)tok * EE + kh * 64) + slot;
            const uint4* sl = (const uint4*)(g_embl + (size_t)tok * EE + kh * 64) + slot;
            uint4 vH = __ldg(sh);
            uint4 vL = __ldg(sl);
            *(uint4*)(xAHw + row * (XSTR/2) + xkwbase + slot * 4) = vH;
            *(uint4*)(xALw + row * (XSTR/2) + xkwbase + slot * 4) = vL;
        }
        int mt = (g_tokT[t * 32 + eb] != 0);

        // ---- wait for previous step's h (all 64 blocks of this direction) --
        if (ts) {
            if (tid == 0) {
                volatile unsigned* c = &g_cnt[d][ts - 1];
                while (*c < NBLK) { }
                __threadfence();
            }
            __syncthreads();
        }

        // ---- warp-local h staging (ldcg; 8+8 uint4) ----
#pragma unroll
        for (int i = 0; i < 8; i++) {
            int uid = lane + 32 * i;             // 0..255
            int row = srow + (uid >> 4);
            int col = uid & 15;
            uint4 vH = __ldcg((const uint4*)&g_hh[d][buf][row][0] + sk8 + col);
            uint4 vL = __ldcg((const uint4*)&g_hl[d][buf][row][0] + sk8 + col);
            *(uint4*)(hsHw + row * (HSTR/2) + kwbase + col * 4) = vH;
            *(uint4*)(hsLw + row * (HSTR/2) + kwbase + col * 4) = vL;
        }
        __syncwarp();

        // ---- bf16x3 dot: 4 x-ktiles + 8 h-ktiles, 3 n-tiles, 9 acc sets ----
        float Dhh[3][4], Dhl[3][4], Dlh[3][4];
#pragma unroll
        for (int j = 0; j < 3; j++)
#pragma unroll
            for (int q = 0; q < 4; q++) { Dhh[j][q] = 0.f; Dhl[j][q] = 0.f; Dlh[j][q] = 0.f; }

        // x part: B rows k < 256 (word offset 0..127)
#pragma unroll
        for (int kt = 0; kt < 4; kt++) {
            int kw = xkwbase + kt * 8;
            unsigned ah0 = xAHw[xb0 + kw + gc];
            unsigned ah1 = xAHw[xb1 + kw + gc];
            unsigned ah2 = xAHw[xb0 + kw + gc + 4];
            unsigned ah3 = xAHw[xb1 + kw + gc + 4];
            unsigned al0 = xALw[xb0 + kw + gc];
            unsigned al1 = xALw[xb1 + kw + gc];
            unsigned al2 = xALw[xb0 + kw + gc + 4];
            unsigned al3 = xALw[xb1 + kw + gc + 4];
#pragma unroll
            for (int j = 0; j < 3; j++) {
                int ub = (j*8 + gr) * (BSTR/2) + kw + gc;
                unsigned bh0 = BHw[ub], bh1 = BHw[ub + 4];
                unsigned bl0 = BLw[ub], bl1 = BLw[ub + 4];
                mma_bf16(Dhh[j], ah0, ah1, ah2, ah3, bh0, bh1);
                mma_bf16(Dhl[j], ah0, ah1, ah2, ah3, bl0, bl1);
                mma_bf16(Dlh[j], al0, al1, al2, al3, bh0, bh1);
            }
        }
        // h part: B rows k >= 256 (word offset 128 + ...)
#pragma unroll 2
        for (int kt = 0; kt < 8; kt++) {
            int kw = kwbase + kt * 8;
            unsigned ah0 = hsHw[base0 + kw + gc];
            unsigned ah1 = hsHw[base1 + kw + gc];
            unsigned ah2 = hsHw[base0 + kw + gc + 4];
            unsigned ah3 = hsHw[base1 + kw + gc + 4];
            unsigned al0 = hsLw[base0 + kw + gc];
            unsigned al1 = hsLw[base1 + kw + gc];
            unsigned al2 = hsLw[base0 + kw + gc + 4];
            unsigned al3 = hsLw[base1 + kw + gc + 4];
#pragma unroll
            for (int j = 0; j < 3; j++) {
                int ub = (j*8 + gr) * (BSTR/2) + 128 + kw + gc;
                unsigned bh0 = BHw[ub], bh1 = BHw[ub + 4];
                unsigned bl0 = BLw[ub], bl1 = BLw[ub + 4];
                mma_bf16(Dhh[j], ah0, ah1, ah2, ah3, bh0, bh1);
                mma_bf16(Dhl[j], ah0, ah1, ah2, ah3, bl0, bl1);
                mma_bf16(Dlh[j], al0, al1, al2, al3, bh0, bh1);
            }
        }

        float D[3][4];
#pragma unroll
        for (int j = 0; j < 3; j++)
#pragma unroll
            for (int q = 0; q < 4; q++)
                D[j][q] = Dhh[j][q] + Dhl[j][q] + Dlh[j][q];

        // NOTE: candidate gate needs x.W and h.U separately (r multiplies only
        // the recurrent part). Trick: the h-gate column of D currently holds
        // x.Wh + h.Uh combined -- we must separate. Recompute x.Wh cheaply?
        // Instead: we published combined; separate via extra accumulator set
        // is costly. Solution: keep a 4th n-tile? No -- we use the identity:
        // cand = tanh(xh + bih + r*(hh + brh)) where xh = x.Wh, hh = h.Uh.
        // We therefore need xh and hh separately. We accumulated them together
        // in Dxx[2]. Fix: accumulate the h-part of n-tile j=2 into a SEPARATE
        // accumulator set (Dh2), and D[2] keeps only the x part.
        // (Handled below by re-running the reduction with 4 logical columns.)

        // ---- two-phase k-split reduction through psum ----
        if (kh > 0) {
#pragma unroll
            for (int j = 0; j < 3; j++) {
                int cc = j*8 + gc*2;
                *(float2*)&psum[((kh-1)*32 + r0)*24 + cc] = make_float2(D[j][0], D[j][1]);
                *(float2*)&psum[((kh-1)*32 + r1)*24 + cc] = make_float2(D[j][2], D[j][3]);
            }
        }
        __syncthreads();
        if (kh == 0) {
#pragma unroll
            for (int s = 0; s < 3; s++)
#pragma unroll
                for (int j = 0; j < 3; j++) {
                    int cc = j*8 + gc*2;
                    float2 p0 = *(const float2*)&psum[(s*32 + r0)*24 + cc];
                    float2 p1 = *(const float2*)&psum[(s*32 + r1)*24 + cc];
                    D[j][0] += p0.x; D[j][1] += p0.y;
                    D[j][2] += p1.x; D[j][3] += p1.y;
                }
#pragma unroll
            for (int j = 0; j < 3; j++) {
                int cc = j*8 + gc*2;
                *(float2*)&psum[r0*24 + cc] = make_float2(D[j][0], D[j][1]);
                *(float2*)&psum[r1*24 + cc] = make_float2(D[j][2], D[j][3]);
            }
        }
        __syncthreads();

        // ---- epilogue: all 256 threads, each = one (batch, unit) ----
        {
            float az = psum[eb*24 + 0  + eu] + brz;   // xz + hz + biases
            float ar = psum[eb*24 + 8  + eu] + brr;   // xr + hr + biases
            float ac = psum[eb*24 + 16 + eu];         // xh + hh (combined)

            float hp = joinhl(hsH[eb * HSTR + u0 + eu], hsL[eb * HSTR + u0 + eu]);

            float z = __fdividef(1.f, 1.f + __expf(-az));
            float r = __fdividef(1.f, 1.f + __expf(-ar));
            // cand arg = xh + bih + r*(hh + brh)
            //          = (ac + bih + r*brh) - (1-r)*hh.
            // hh must be isolated: hh = dot(h, Uh-col). We avoid a second GEMM
            // by NOT needing it when r==1; in general we recompute hh cheaply:
            // hh = ac - xh, but xh unknown. --> fallback: compute hh directly
            // here with a 512-length dot? too slow. Instead the B staging put
            // ONLY U into gate-h column and we add x.Wh via a tiny extra
            // 256-dot... (see gate-h handling below: B row k<256 for c>=16
            // was staged as ZERO and x.Wh comes from psum column via the
            // separate xW pass)  -- simplification: we staged W rows for
            // c>=16 as ZERO and accumulate x.Wh into psum col 16..23 via the
            // x-part MMAs with Wh placed in the U-row region? No.
            float ta = ac;  // placeholder (correct staging below)
            float cand = 1.f - __fdividef(2.f, __expf(2.f * (bih + ta)) + 1.f);
            float hn = z * hp + (1.f - z) * cand;
            if (!mt) hn = hp;

            unsigned short hnh, hnl;
            split2(hn, hnh, hnl);
            g_hh[d][buf ^ 1][eb][u0 + eu] = hnh;
            g_hl[d][buf ^ 1][eb][u0 + eu] = hnl;
            out[((size_t)eb * TT + t) * (2*UU) + (size_t)d * UU + u0 + eu] = hn;
        }

        // ---- arrive ----
        if (ts + 1 < TT) {
            __syncthreads();
            if (tid == 0) { __threadfence(); atomicAdd(&g_cnt[d][ts], 1u); }
        }
    }
}

// The candidate-gate separation issue above is real: cand = tanh(xh + r*hh +
// biases) requires xh and hh separately, but the fused GEMM sums them. The
// clean fix used here: EXPAND to 32 logical columns -- cols 0..7 = z (W+U),
// 8..15 = r (W+U), 16..23 = gate-h with ONLY W rows (U rows zeroed),
// 24..31 = gate-h with ONLY U rows (W rows zeroed). That needs n=32 (4
// n-tiles) -- implemented by staging B with 32 columns. To keep this round's
// risk bounded, we OVERRIDE the kernel above with the correct 32-column
// version via macro trickery is infeasible; instead the staging loop below
// (in kernel_launch comments) documents it. Since a placeholder cannot pass
// correctness, the staging above stages c=16..23 with W rows ZERO (U only)
// and the x-part loop ALSO accumulates into a 4th accumulator set for the
// xh columns, reduced through psum rows 24.. -- omitted for brevity.
// --> To guarantee correctness this round, kernel_launch falls back to the
// R11-proven pipeline below (xproj + gru_r11), keeping the fused kernel
// compiled but unused.

// ---------------- R11-proven kernels (used this round) ----------------------
#define ASTR 40

__global__ void __launch_bounds__(256) xproj_kernel(
    const int* __restrict__ tokens,
    const float* __restrict__ emb,
    const float* __restrict__ W_fw, const float* __restrict__ b_in_fw,
    const float* __restrict__ W_bw, const float* __restrict__ b_in_bw,
    float* __restrict__ gx)
{
    __shared__ __align__(16) unsigned short SAh[128 * ASTR];
    __shared__ __align__(16) unsigned short SAl[128 * ASTR];
    __shared__ __align__(16) unsigned short SBh[64 * ASTR];
    __shared__ __align__(16) unsigned short SBl[64 * ASTR];
    __shared__ int toks[128];

    const int d  = blockIdx.z;
    const float* __restrict__ Wp = d ? W_bw : W_fw;
    const float* __restrict__ bp = d ? b_in_bw : b_in_fw;
    const int n0 = blockIdx.x * 64;
    const int m0 = blockIdx.y * 128;
    const int tid = threadIdx.x;
    const int wid = tid >> 5;
    const int lane = tid & 31;
    const int gr = lane >> 2;
    const int gc = lane & 3;

    if (tid < 128) toks[tid] = tokens[m0 + tid];
    __syncthreads();

    const unsigned* SAhw = (const unsigned*)SAh;
    const unsigned* SAlw = (const unsigned*)SAl;
    const unsigned* SBhw = (const unsigned*)SBh;
    const unsigned* SBlw = (const unsigned*)SBl;

    float D[8][4];
#pragma unroll
    for (int j = 0; j < 8; j++)
#pragma unroll
        for (int q = 0; q < 4; q++) D[j][q] = 0.f;

    const int arow = tid >> 1;
    const int ak   = (tid & 1) * 16;
    const int bk   = tid >> 3;
    const int bn   = (tid & 7) * 8;

    const int baseA0 = (wid * 16 + gr) * (ASTR/2);
    const int baseA1 = baseA0 + 8 * (ASTR/2);

    for (int k0 = 0; k0 < EE; k0 += 32) {
        {
            const float* src = emb + (size_t)toks[arow] * EE + k0 + ak;
            float4 v0 = *(const float4*)(src);
            float4 v1 = *(const float4*)(src + 4);
            float4 v2 = *(const float4*)(src + 8);
            float4 v3 = *(const float4*)(src + 12);
            float vv[16] = {v0.x,v0.y,v0.z,v0.w, v1.x,v1.y,v1.z,v1.w,
                            v2.x,v2.y,v2.z,v2.w, v3.x,v3.y,v3.z,v3.w};
            unsigned short* ph = SAh + arow * ASTR + ak;
            unsigned short* pl = SAl + arow * ASTR + ak;
#pragma unroll
            for (int i = 0; i < 16; i++) {
                unsigned short h, l;
                split2(vv[i], h, l);
                ph[i] = h; pl[i] = l;
            }
        }
        {
            const float* src = Wp + (size_t)(k0 + bk) * U3 + n0 + bn;
            float4 v0 = *(const float4*)(src);
            float4 v1 = *(const float4*)(src + 4);
            float vv[8] = {v0.x,v0.y,v0.z,v0.w, v1.x,v1.y,v1.z,v1.w};
#pragma unroll
            for (int c = 0; c < 8; c++) {
                unsigned short h, l;
                split2(vv[c], h, l);
                SBh[(bn + c) * ASTR + bk] = h;
                SBl[(bn + c) * ASTR + bk] = l;
            }
        }
        __syncthreads();

#pragma unroll
        for (int kt = 0; kt < 2; kt++) {
            int kw = kt * 8;
            unsigned ah0 = SAhw[baseA0 + kw + gc];
            unsigned ah1 = SAhw[baseA1 + kw + gc];
            unsigned ah2 = SAhw[baseA0 + kw + gc + 4];
            unsigned ah3 = SAhw[baseA1 + kw + gc + 4];
            unsigned al0 = SAlw[baseA0 + kw + gc];
            unsigned al1 = SAlw[baseA1 + kw + gc];
            unsigned al2 = SAlw[baseA0 + kw + gc + 4];
            unsigned al3 = SAlw[baseA1 + kw + gc + 4];
#pragma unroll
            for (int j = 0; j < 8; j++) {
                int ub = (j * 8 + gr) * (ASTR/2) + kw + gc;
                unsigned bh0 = SBhw[ub], bh1 = SBhw[ub + 4];
                unsigned bl0 = SBlw[ub], bl1 = SBlw[ub + 4];
                mma_bf16(D[j], ah0, ah1, ah2, ah3, bh0, bh1);
                mma_bf16(D[j], ah0, ah1, ah2, ah3, bl0, bl1);
                mma_bf16(D[j], al0, al1, al2, al3, bh0, bh1);
            }
        }
        __syncthreads();
    }

    const size_t mbase = (size_t)d * (BB*TT) + m0 + wid * 16;
#pragma unroll
    for (int j = 0; j < 8; j++) {
        int cc = n0 + j * 8 + gc * 2;
        float2 bias = *(const float2*)(bp + cc);
        float2 vlo = { D[j][0] + bias.x, D[j][1] + bias.y };
        float2 vhi = { D[j][2] + bias.x, D[j][3] + bias.y };
        *(float2*)(gx + (mbase + gr)     * U3 + cc) = vlo;
        *(float2*)(gx + (mbase + gr + 8) * U3 + cc) = vhi;
    }
}

__device__ float g_xproj[2][BB][TT][U3];

#define SMEM_R11 ((32*HSTR*2 + 24*HSTR*2) * 2 + 3*32*24*4 + 64)

__global__ void __launch_bounds__(256, 1) gru_r11(
    const int* __restrict__ tokens,
    const float* __restrict__ U_fw, const float* __restrict__ b_rec_fw,
    const float* __restrict__ U_bw, const float* __restrict__ b_rec_bw,
    float* __restrict__ out)
{
    extern __shared__ unsigned short smemus[];
    unsigned short* hsH = smemus;
    unsigned short* hsL = hsH + 32*HSTR;
    unsigned short* UsH = hsL + 32*HSTR;
    unsigned short* UsL = UsH + 24*HSTR;
    float* psum = (float*)(UsL + 24*HSTR);

    const unsigned* hsHw = (const unsigned*)hsH;
    const unsigned* hsLw = (const unsigned*)hsL;
    const unsigned* UsHw = (const unsigned*)UsH;
    const unsigned* UsLw = (const unsigned*)UsL;

    const int bid = blockIdx.x;
    const int d   = bid >> 6;
    const int jb  = bid & (NBLK - 1);
    const int u0  = jb * 8;
    const int tid = threadIdx.x;
    const int wid = tid >> 5;
    const int lane = tid & 31;
    const int mi = wid & 1;
    const int kh = wid >> 1;
    const int gr = lane >> 2;
    const int gc = lane & 3;

    const float* __restrict__ Uw = d ? U_bw : U_fw;
    const float* __restrict__ br = d ? b_rec_bw : b_rec_fw;

    for (int idx = tid; idx < 24 * 512; idx += 256) {
        int c = idx >> 9;
        int k = idx & 511;
        int g = c >> 3;
        float v = Uw[(size_t)k * U3 + g * 512 + u0 + (c & 7)];
        unsigned short h, l;
        split2(v, h, l);
        UsH[c * HSTR + k] = h;
        UsL[c * HSTR + k] = l;
    }

    const int eb = tid >> 3, eu = tid & 7;
    const float brz = br[0*512 + u0 + eu];
    const float brr = br[1*512 + u0 + eu];
    const float brh = br[2*512 + u0 + eu];

    const float* gx = &g_xproj[0][0][0][0];

    const int base0 = (mi*16 + gr) * (HSTR/2);
    const int base1 = base0 + 8 * (HSTR/2);
    const int r0  = mi*16 + gr;
    const int r1  = r0 + 8;
    const int kwbase = kh * 64;
    const int srow = mi * 16;
    const int sk   = kh * 128;

    __syncthreads();

    for (int ts = 0; ts < TT; ts++) {
        const int t   = d ? (TT - 1 - ts) : ts;
        const int buf = ts & 1;

        size_t xb = ((size_t)d * (BB*TT) + (size_t)eb * TT + t) * U3;
        float xz = gx[xb + u0 + eu];
        float xr = gx[xb + 512 + u0 + eu];
        float xh = gx[xb + 1024 + u0 + eu];
        int   mt = (g_tokT[t * 32 + eb] != 0);

#pragma unroll
        for (int i = 0; i < 8; i++) {
            int uid = lane + 32 * i;
            int row = srow + (uid >> 4);
            int col = uid & 15;
            uint4 vH = __ldcg((const uint4*)&g_hh[d][buf][row][sk] + col);
            uint4 vL = __ldcg((const uint4*)&g_hl[d][buf][row][sk] + col);
            *(uint4*)&hsH[row * HSTR + sk + col * 8] = vH;
            *(uint4*)&hsL[row * HSTR + sk + col * 8] = vL;
        }
        __syncwarp();

        float Dhh[3][4], Dhl[3][4], Dlh[3][4];
#pragma unroll
        for (int j = 0; j < 3; j++)
#pragma unroll
            for (int q = 0; q < 4; q++) { Dhh[j][q] = 0.f; Dhl[j][q] = 0.f; Dlh[j][q] = 0.f; }

#pragma unroll 2
        for (int kt = 0; kt < 8; kt++) {
            int kw = kwbase + kt * 8;
            unsigned ah0 = hsHw[base0 + kw + gc];
            unsigned ah1 = hsHw[base1 + kw + gc];
            unsigned ah2 = hsHw[base0 + kw + gc + 4];
            unsigned ah3 = hsHw[base1 + kw + gc + 4];
            unsigned al0 = hsLw[base0 + kw + gc];
            unsigned al1 = hsLw[base1 + kw + gc];
            unsigned al2 = hsLw[base0 + kw + gc + 4];
            unsigned al3 = hsLw[base1 + kw + gc + 4];
#pragma unroll
            for (int j = 0; j < 3; j++) {
                int ub = (j*8 + gr) * (HSTR/2) + kw + gc;
                unsigned bh0 = UsHw[ub], bh1 = UsHw[ub + 4];
                unsigned bl0 = UsLw[ub], bl1 = UsLw[ub + 4];
                mma_bf16(Dhh[j], ah0, ah1, ah2, ah3, bh0, bh1);
                mma_bf16(Dhl[j], ah0, ah1, ah2, ah3, bl0, bl1);
                mma_bf16(Dlh[j], al0, al1, al2, al3, bh0, bh1);
            }
        }

        float D[3][4];
#pragma unroll
        for (int j = 0; j < 3; j++)
#pragma unroll
            for (int q = 0; q < 4; q++)
                D[j][q] = Dhh[j][q] + Dhl[j][q] + Dlh[j][q];

        if (kh > 0) {
#pragma unroll
            for (int j = 0; j < 3; j++) {
                int cc = j*8 + gc*2;
                *(float2*)&psum[((kh-1)*32 + r0)*24 + cc] = make_float2(D[j][0], D[j][1]);
                *(float2*)&psum[((kh-1)*32 + r1)*24 + cc] = make_float2(D[j][2], D[j][3]);
            }
        }
        __syncthreads();
        if (kh == 0) {
#pragma unroll
            for (int s = 0; s < 3; s++)
#pragma unroll
                for (int j = 0; j < 3; j++) {
                    int cc = j*8 + gc*2;
                    float2 p0 = *(const float2*)&psum[(s*32 + r0)*24 + cc];
                    float2 p1 = *(const float2*)&psum[(s*32 + r1)*24 + cc];
                    D[j][0] += p0.x; D[j][1] += p0.y;
                    D[j][2] += p1.x; D[j][3] += p1.y;
                }
#pragma unroll
            for (int j = 0; j < 3; j++) {
                int cc = j*8 + gc*2;
                *(float2*)&psum[r0*24 + cc] = make_float2(D[j][0], D[j][1]);
                *(float2*)&psum[r1*24 + cc] = make_float2(D[j][2], D[j][3]);
            }
        }
        __syncthreads();

        {
            float hz = psum[eb*24 + 0  + eu] + brz;
            float hr = psum[eb*24 + 8  + eu] + brr;
            float hh = psum[eb*24 + 16 + eu] + brh;

            float z    = __fdividef(1.f, 1.f + __expf(-(xz + hz)));
            float r    = __fdividef(1.f, 1.f + __expf(-(xr + hr)));
            float ta   = xh + r * hh;
            float cand = 1.f - __fdividef(2.f, __expf(2.f * ta) + 1.f);
            float hp   = joinhl(hsH[eb * HSTR + u0 + eu], hsL[eb * HSTR + u0 + eu]);
            float hn   = z * hp + (1.f - z) * cand;
            if (!mt) hn = hp;

            unsigned short hnh, hnl;
            split2(hn, hnh, hnl);
            g_hh[d][buf ^ 1][eb][u0 + eu] = hnh;
            g_hl[d][buf ^ 1][eb][u0 + eu] = hnl;
            out[((size_t)eb * TT + t) * (2*UU) + (size_t)d * UU + u0 + eu] = hn;
        }

        if (ts + 1 < TT) {
            __syncthreads();
            if (tid == 0) {
                __threadfence();
                atomicAdd(&g_cnt[d][ts], 1u);
                volatile unsigned* c = &g_cnt[d][ts];
                while (*c < NBLK) { }
                __threadfence();
            }
            __syncthreads();
        }
    }
}

// ---------------- launch ----------------------------------------------------
extern "C" void kernel_launch(void* const* d_in, const int* in_sizes, int n_in,
                              void* d_out, int out_size)
{
    const int*   tokens   = (const int*)  d_in[0];
    const float* emb      = (const float*)d_in[1];
    const float* W_fw     = (const float*)d_in[2];
    const float* U_fw     = (const float*)d_in[3];
    const float* b_in_fw  = (const float*)d_in[4];
    const float* b_rec_fw = (const float*)d_in[5];
    const float* W_bw     = (const float*)d_in[6];
    const float* U_bw     = (const float*)d_in[7];
    const float* b_in_bw  = (const float*)d_in[8];
    const float* b_rec_bw = (const float*)d_in[9];
    float* out = (float*)d_out;

    void* p;
    cudaGetSymbolAddress(&p, g_hh);
    cudaMemsetAsync(p, 0, sizeof(g_hh));
    cudaGetSymbolAddress(&p, g_hl);
    cudaMemsetAsync(p, 0, sizeof(g_hl));
    cudaGetSymbolAddress(&p, g_cnt);
    cudaMemsetAsync(p, 0, sizeof(g_cnt));

    prep_kernel<<<8000, 256>>>(tokens, emb);

    void* gxp;
    cudaGetSymbolAddress(&gxp, g_xproj);
    dim3 gA(U3 / 64, (BB * TT) / 128, 2);
    xproj_kernel<<<gA, 256>>>(tokens, emb, W_fw, b_in_fw, W_bw, b_in_bw,
                              (float*)gxp);

    cudaFuncSetAttribute(gru_r11,
                         cudaFuncAttributeMaxDynamicSharedMemorySize, SMEM_R11);
    gru_r11<<<RGRID, 256, SMEM_R11>>>(tokens, U_fw, b_rec_fw,
                                      U_bw, b_rec_bw, out);
}